// round 3
// baseline (speedup 1.0000x reference)
#include <cuda_runtime.h>

// ---------------------------------------------------------------------------
// 4-level DWT lowpass analysis + synthesis (trend), season = x - trend.
// One CTA per row. SMEM holds only the two ping-pong stage buffers (98.4 KB)
// so 2 CTAs fit per SM (2048 threads = full occupancy).
//
// Analysis (stride-2 correlation, zero pad):  y[i] = sum_k x[2i-6+k]*DEC_LO[7-k]
//   lengths: 32768 -> 16387 -> 8197 -> 4102 -> 2054
// Synthesis (transposed conv, out = 2*n_in - 6), split by parity:
//   t[2q]   = lo[q]*D1 + lo[q+1]*D3 + lo[q+2]*D5 + lo[q+3]*D7
//   t[2q+1] = lo[q]*D0 + lo[q+1]*D2 + lo[q+2]*D4 + lo[q+3]*D6
//   pairs (= n_in-3): 2051, 4099, 8194(trim 8198->8197), 16384(trim 16388->16387)
// Max read index = n_in-1 at every synthesis stage: no bounds checks needed.
// ---------------------------------------------------------------------------

#define THREADS 1024
#define ROW_N   32768
#define N1      16387
#define N2      8197
#define N3      4102
#define N4      2054

#define D0 (-0.010597401784997278f)
#define D1 ( 0.032883011666982945f)
#define D2 ( 0.030841381835986965f)
#define D3 (-0.18703481171888114f)
#define D4 (-0.02798376941698385f)
#define D5 ( 0.6308807679295904f)
#define D6 ( 0.7148465705525415f)
#define D7 ( 0.23037781330885523f)

// Padded ping-pong buffers (floats). Writes reach idx 16391 / 8199; reads 16387/8199.
#define B0_SZ 16392
#define B1_SZ 8204
#define SMEM_BYTES ((B0_SZ + B1_SZ) * 4)

// 8-tap decimating correlation contribution from 4 float2's (p,q,r,s cover 8 taps)
#define AFB_ACC(p, q, r, s)                                                   \
    fmaf((s).y, D0, fmaf((s).x, D1, fmaf((r).y, D2, fmaf((r).x, D3,           \
    fmaf((q).y, D4, fmaf((q).x, D5, fmaf((p).y, D6, (p).x * D7)))))))

// Analysis stage: 4 outputs per chunk, vectorized interior, scalar zero-pad edges.
static __device__ __forceinline__ void afb_stage(const float* __restrict__ in, int n_in,
                                                 float* __restrict__ out, int n_out) {
    const int nchunk = (n_out + 3) >> 2;
    for (int c = threadIdx.x; c < nchunk; c += THREADS) {
        const int i0 = c << 2;
        const int base = 2 * i0 - 6;                 // even -> float2 aligned
        if (base >= 0 && base + 13 < n_in) {
            const float2 v0 = *reinterpret_cast<const float2*>(in + base);
            const float2 v1 = *reinterpret_cast<const float2*>(in + base + 2);
            const float2 v2 = *reinterpret_cast<const float2*>(in + base + 4);
            const float2 v3 = *reinterpret_cast<const float2*>(in + base + 6);
            const float2 v4 = *reinterpret_cast<const float2*>(in + base + 8);
            const float2 v5 = *reinterpret_cast<const float2*>(in + base + 10);
            const float2 v6 = *reinterpret_cast<const float2*>(in + base + 12);
            float4 o;
            o.x = AFB_ACC(v0, v1, v2, v3);
            o.y = AFB_ACC(v1, v2, v3, v4);
            o.z = AFB_ACC(v2, v3, v4, v5);
            o.w = AFB_ACC(v3, v4, v5, v6);
            *reinterpret_cast<float4*>(out + i0) = o;   // i0 % 4 == 0, padded buffer
        } else {
            const float hh[8] = {D7, D6, D5, D4, D3, D2, D1, D0};
            #pragma unroll
            for (int r = 0; r < 4; ++r) {
                const int i = i0 + r;
                if (i < n_out) {
                    const int b = 2 * i - 6;
                    float a = 0.0f;
                    #pragma unroll
                    for (int k = 0; k < 8; ++k) {
                        const int j = b + k;
                        if (j >= 0 && j < n_in) a = fmaf(in[j], hh[k], a);
                    }
                    out[i] = a;
                }
            }
        }
    }
}

// One synthesis pair from 4 consecutive lowpass samples.
#define SFB_PAIR(a, b, c, d, te, to)                                          \
    do {                                                                      \
        te = fmaf((d), D7, fmaf((c), D5, fmaf((b), D3, (a) * D1)));           \
        to = fmaf((d), D6, fmaf((c), D4, fmaf((b), D2, (a) * D0)));           \
    } while (0)

// Synthesis stage in SMEM: 4 pairs (8 outputs) per chunk via float4.
static __device__ __forceinline__ void sfb_stage(const float* __restrict__ in,
                                                 float* __restrict__ out, int n_pairs) {
    const int nchunk = (n_pairs + 3) >> 2;
    for (int c = threadIdx.x; c < nchunk; c += THREADS) {
        const int q0 = c << 2;
        const float4 u = *reinterpret_cast<const float4*>(in + q0);
        const float4 w = *reinterpret_cast<const float4*>(in + q0 + 4);
        float4 t0, t1;
        SFB_PAIR(u.x, u.y, u.z, u.w, t0.x, t0.y);
        SFB_PAIR(u.y, u.z, u.w, w.x, t0.z, t0.w);
        SFB_PAIR(u.z, u.w, w.x, w.y, t1.x, t1.y);
        SFB_PAIR(u.w, w.x, w.y, w.z, t1.z, t1.w);
        *reinterpret_cast<float4*>(out + 2 * q0)     = t0;
        *reinterpret_cast<float4*>(out + 2 * q0 + 4) = t1;
    }
}

__global__ __launch_bounds__(THREADS, 2)
void wt_decomp_kernel(const float* __restrict__ x,
                      float* __restrict__ season,
                      float* __restrict__ trend) {
    extern __shared__ float smem[];
    float* B0 = smem;            // B0_SZ floats
    float* B1 = smem + B0_SZ;    // B1_SZ floats

    const size_t off = (size_t)blockIdx.x * ROW_N;
    const float* xr = x + off;

    // Analysis chain (details unused). Stage 1 streams x from GMEM.
    afb_stage(xr, ROW_N, B0, N1); __syncthreads();   // lo1 -> B0
    afb_stage(B0, N1,   B1, N2); __syncthreads();    // lo2 -> B1
    afb_stage(B1, N2,   B0, N3); __syncthreads();    // lo3 -> B0 (lo1 dead)
    afb_stage(B0, N3,   B1, N4); __syncthreads();    // lo4 -> B1 (lo2 dead)

    // Synthesis chain
    sfb_stage(B1, B0, N3 - 3);   __syncthreads();    // 2054 -> 4102  (B0)
    sfb_stage(B0, B1, 4102 - 3); __syncthreads();    // 4102 -> 8198  (B1)
    sfb_stage(B1, B0, 8197 - 3); __syncthreads();    // 8197*-> 16388 (B0)

    // Final: 16387* -> 32768, fused with season = x - trend, straight to GMEM.
    float* tre = trend + off;
    float* sea = season + off;
    const int nchunk = (ROW_N / 2) >> 2;             // 4096 chunks of 4 pairs
    for (int c = threadIdx.x; c < nchunk; c += THREADS) {
        const int q0 = c << 2;
        const float4 u = *reinterpret_cast<const float4*>(B0 + q0);
        const float4 w = *reinterpret_cast<const float4*>(B0 + q0 + 4);
        float4 t0, t1;
        SFB_PAIR(u.x, u.y, u.z, u.w, t0.x, t0.y);
        SFB_PAIR(u.y, u.z, u.w, w.x, t0.z, t0.w);
        SFB_PAIR(u.z, u.w, w.x, w.y, t1.x, t1.y);
        SFB_PAIR(u.w, w.x, w.y, w.z, t1.z, t1.w);
        const float4 x0 = __ldg(reinterpret_cast<const float4*>(xr + 2 * q0));
        const float4 x1 = __ldg(reinterpret_cast<const float4*>(xr + 2 * q0 + 4));
        *reinterpret_cast<float4*>(tre + 2 * q0)     = t0;
        *reinterpret_cast<float4*>(tre + 2 * q0 + 4) = t1;
        float4 s0, s1;
        s0.x = x0.x - t0.x; s0.y = x0.y - t0.y; s0.z = x0.z - t0.z; s0.w = x0.w - t0.w;
        s1.x = x1.x - t1.x; s1.y = x1.y - t1.y; s1.z = x1.z - t1.z; s1.w = x1.w - t1.w;
        *reinterpret_cast<float4*>(sea + 2 * q0)     = s0;
        *reinterpret_cast<float4*>(sea + 2 * q0 + 4) = s1;
    }
}

extern "C" void kernel_launch(void* const* d_in, const int* in_sizes, int n_in,
                              void* d_out, int out_size) {
    (void)n_in; (void)out_size;
    const float* x = (const float*)d_in[0];
    float* out = (float*)d_out;

    const int nsig = in_sizes[0] / ROW_N;
    const size_t total = (size_t)nsig * ROW_N;
    float* season = out;            // output tuple order: (season, trend)
    float* trend  = out + total;

    cudaFuncSetAttribute(wt_decomp_kernel,
                         cudaFuncAttributeMaxDynamicSharedMemorySize, SMEM_BYTES);
    wt_decomp_kernel<<<nsig, THREADS, SMEM_BYTES>>>(x, season, trend);
}

// round 6
// speedup vs baseline: 1.1751x; 1.1751x over previous
#include <cuda_runtime.h>

// ---------------------------------------------------------------------------
// 4-level DWT lowpass analysis + synthesis (trend), season = x - trend.
// One CTA per row, 2 CTAs/SM. All SMEM stage buffers stored POLYPHASE
// (E-plane = even samples, O-plane = odd samples) so every LDS/STS is a
// contiguous, conflict-free float2/float4 access.
//
// Analysis:  y[i] = sum_k x[2i-6+k]*DEC_LO[7-k]
//   = E[i-3]D7+O[i-3]D6+E[i-2]D5+O[i-2]D4+E[i-1]D3+O[i-1]D2+E[i]D1+O[i]D0
//   lengths: 32768 -> 16387 -> 8197 -> 4102 -> 2054
// Synthesis: t[2q]=aD1+bD3+cD5+dD7, t[2q+1]=aD0+bD2+cD4+dD6, a..d=in[q..q+3]
//   pairs: 2051 -> 4099 -> 8194 -> 16384 (trims at 8198->8197, 16388->16387)
// Each plane has 4 zeroed front-pad and 12-slot tail (zeroed for analysis
// buffers) so interior code needs no bounds checks. Edge-chunk "spurious"
// outputs are provably exact zeros (they read only zeroed tails), so the
// unsynced overlap with ZERO_PADS writes identical values (benign).
// ---------------------------------------------------------------------------

#define THREADS 1024

#define D0 (-0.010597401784997278f)
#define D1 ( 0.032883011666982945f)
#define D2 ( 0.030841381835986965f)
#define D3 (-0.18703481171888114f)
#define D4 (-0.02798376941698385f)
#define D5 ( 0.6308807679295904f)
#define D6 ( 0.7148465705525415f)
#define D7 ( 0.23037781330885523f)

// Buffer A: lo1/S3 (nE=8194,nO=8193/8194), capacity per plane 8208
// Buffer B: lo2/S2 (nE=4099,nO=4098/4099), capacity per plane 4112
#define A_SZ  16424              // 4 + 8208 + 4 + 8208
#define B_SZ  8232               // 4 + 4112 + 4 + 4112
#define SMEM_BYTES ((A_SZ + B_SZ) * 4)

#define LO1_E 4
#define LO1_O 8216
#define LO2_E 4
#define LO2_O 4120
#define LO3_E 4                  // lo3/S1: nE=nO=2051, cap 2064
#define LO3_O 2072
#define LO4_E 4                  // lo4: nE=nO=1027, cap 1040
#define LO4_O 1048

// Zero the 4 front + 12 tail pad slots of both output planes.
#define ZERO_PADS(Eo, Oo, nEo, nOo)                                           \
    do {                                                                      \
        const int _t = threadIdx.x;                                           \
        if (_t < 4)       { (Eo)[_t - 4] = 0.f; (Oo)[_t - 4] = 0.f; }         \
        else if (_t < 16) { (Eo)[(nEo) + _t - 4] = 0.f;                       \
                            (Oo)[(nOo) + _t - 4] = 0.f; }                     \
    } while (0)

// ---- Analysis from polyphase planes: 4 outputs/thread, all float4 LDS ----
static __device__ __forceinline__ void afb_p(const float* __restrict__ Ei,
                                             const float* __restrict__ Oi,
                                             float* __restrict__ Eo,
                                             float* __restrict__ Oo,
                                             int n_out, int nEo, int nOo) {
    ZERO_PADS(Eo, Oo, nEo, nOo);
    const int nchunk = (n_out + 3) >> 2;
    for (int c = threadIdx.x; c < nchunk; c += THREADS) {
        const int i0 = c << 2;
        const float4 e0 = *reinterpret_cast<const float4*>(Ei + i0 - 4);
        const float4 e1 = *reinterpret_cast<const float4*>(Ei + i0);
        const float4 o0 = *reinterpret_cast<const float4*>(Oi + i0 - 4);
        const float4 o1 = *reinterpret_cast<const float4*>(Oi + i0);
        const float y0 = fmaf(o1.x, D0, fmaf(e1.x, D1, fmaf(o0.w, D2, fmaf(e0.w, D3,
                         fmaf(o0.z, D4, fmaf(e0.z, D5, fmaf(o0.y, D6, e0.y * D7)))))));
        const float y1 = fmaf(o1.y, D0, fmaf(e1.y, D1, fmaf(o1.x, D2, fmaf(e1.x, D3,
                         fmaf(o0.w, D4, fmaf(e0.w, D5, fmaf(o0.z, D6, e0.z * D7)))))));
        const float y2 = fmaf(o1.z, D0, fmaf(e1.z, D1, fmaf(o1.y, D2, fmaf(e1.y, D3,
                         fmaf(o1.x, D4, fmaf(e1.x, D5, fmaf(o0.w, D6, e0.w * D7)))))));
        const float y3 = fmaf(o1.w, D0, fmaf(e1.w, D1, fmaf(o1.z, D2, fmaf(e1.z, D3,
                         fmaf(o1.y, D4, fmaf(e1.y, D5, fmaf(o1.x, D6, e1.x * D7)))))));
        *reinterpret_cast<float2*>(Eo + (i0 >> 1)) = make_float2(y0, y2);
        *reinterpret_cast<float2*>(Oo + (i0 >> 1)) = make_float2(y1, y3);
    }
}

// ---- Stage 1: analysis straight from GMEM x (natural order) ----
static __device__ __forceinline__ void afb_g(const float* __restrict__ x,
                                             float* __restrict__ Eo,
                                             float* __restrict__ Oo) {
    ZERO_PADS(Eo, Oo, 8194, 8193);
    const int nchunk = 4097;                       // ceil(16387/4)
    for (int c = threadIdx.x; c < nchunk; c += THREADS) {
        const int i0 = c << 2;
        if (i0 >= 4 && i0 <= 16380) {
            // x[2i0-8 .. 2i0+7] via 4 aligned float4 (32B-aligned base)
            const float4* xb = reinterpret_cast<const float4*>(x + 2 * i0 - 8);
            const float4 a = xb[0], b = xb[1], g = xb[2], d = xb[3];
            const float y0 = fmaf(g.y, D0, fmaf(g.x, D1, fmaf(b.w, D2, fmaf(b.z, D3,
                             fmaf(b.y, D4, fmaf(b.x, D5, fmaf(a.w, D6, a.z * D7)))))));
            const float y1 = fmaf(g.w, D0, fmaf(g.z, D1, fmaf(g.y, D2, fmaf(g.x, D3,
                             fmaf(b.w, D4, fmaf(b.z, D5, fmaf(b.y, D6, b.x * D7)))))));
            const float y2 = fmaf(d.y, D0, fmaf(d.x, D1, fmaf(g.w, D2, fmaf(g.z, D3,
                             fmaf(g.y, D4, fmaf(g.x, D5, fmaf(b.w, D6, b.z * D7)))))));
            const float y3 = fmaf(d.w, D0, fmaf(d.z, D1, fmaf(d.y, D2, fmaf(d.x, D3,
                             fmaf(g.w, D4, fmaf(g.z, D5, fmaf(g.y, D6, g.x * D7)))))));
            *reinterpret_cast<float2*>(Eo + (i0 >> 1)) = make_float2(y0, y2);
            *reinterpret_cast<float2*>(Oo + (i0 >> 1)) = make_float2(y1, y3);
        } else {
            const float hh[8] = {D7, D6, D5, D4, D3, D2, D1, D0};
            #pragma unroll
            for (int r = 0; r < 4; ++r) {
                const int i = i0 + r;
                if (i < 16387) {
                    const int bidx = 2 * i - 6;
                    float acc = 0.f;
                    #pragma unroll
                    for (int k = 0; k < 8; ++k) {
                        const int j = bidx + k;
                        if (j >= 0 && j < 32768) acc = fmaf(x[j], hh[k], acc);
                    }
                    if (i & 1) Oo[i >> 1] = acc; else Eo[i >> 1] = acc;
                }
            }
        }
    }
}

// ---- Synthesis planes->planes: 4 pairs/thread, float2 in / float4 out ----
#define SFB_CHUNK(Ei, Oi, m0, te, to)                                         \
    const float2 ea = *reinterpret_cast<const float2*>((Ei) + (m0));          \
    const float2 eb = *reinterpret_cast<const float2*>((Ei) + (m0) + 2);      \
    const float2 oa = *reinterpret_cast<const float2*>((Oi) + (m0));          \
    const float2 ob = *reinterpret_cast<const float2*>((Oi) + (m0) + 2);      \
    te.x = fmaf(oa.y, D7, fmaf(ea.y, D5, fmaf(oa.x, D3, ea.x * D1)));         \
    to.x = fmaf(oa.y, D6, fmaf(ea.y, D4, fmaf(oa.x, D2, ea.x * D0)));         \
    te.y = fmaf(eb.x, D7, fmaf(oa.y, D5, fmaf(ea.y, D3, oa.x * D1)));         \
    to.y = fmaf(eb.x, D6, fmaf(oa.y, D4, fmaf(ea.y, D2, oa.x * D0)));         \
    te.z = fmaf(ob.x, D7, fmaf(eb.x, D5, fmaf(oa.y, D3, ea.y * D1)));         \
    to.z = fmaf(ob.x, D6, fmaf(eb.x, D4, fmaf(oa.y, D2, ea.y * D0)));         \
    te.w = fmaf(eb.y, D7, fmaf(ob.x, D5, fmaf(eb.x, D3, oa.y * D1)));         \
    to.w = fmaf(eb.y, D6, fmaf(ob.x, D4, fmaf(eb.x, D2, oa.y * D0)))

static __device__ __forceinline__ void sfb_p(const float* __restrict__ Ei,
                                             const float* __restrict__ Oi,
                                             float* __restrict__ Eo,
                                             float* __restrict__ Oo,
                                             int n_pairs) {
    const int nchunk = (n_pairs + 3) >> 2;
    for (int c = threadIdx.x; c < nchunk; c += THREADS) {
        const int m0 = c << 1;
        float4 te, to;
        SFB_CHUNK(Ei, Oi, m0, te, to);
        *reinterpret_cast<float4*>(Eo + (c << 2)) = te;
        *reinterpret_cast<float4*>(Oo + (c << 2)) = to;
    }
}

__global__ __launch_bounds__(THREADS, 2)
void wt_decomp_kernel(const float* __restrict__ x,
                      float* __restrict__ season,
                      float* __restrict__ trend) {
    extern __shared__ float sm[];
    float* A = sm;
    float* B = sm + A_SZ;

    const size_t off = (size_t)blockIdx.x * 32768;
    const float* xr = x + off;

    // Analysis: x -> lo1(A) -> lo2(B) -> lo3(A) -> lo4(B)
    afb_g(xr, A + LO1_E, A + LO1_O);                                     __syncthreads();
    afb_p(A + LO1_E, A + LO1_O, B + LO2_E, B + LO2_O, 8197, 4099, 4098); __syncthreads();
    afb_p(B + LO2_E, B + LO2_O, A + LO3_E, A + LO3_O, 4102, 2051, 2051); __syncthreads();
    afb_p(A + LO3_E, A + LO3_O, B + LO4_E, B + LO4_O, 2054, 1027, 1027); __syncthreads();

    // Synthesis: lo4(B) -> S1(A) -> S2(B) -> S3(A) -> trend/season (GMEM)
    sfb_p(B + LO4_E, B + LO4_O, A + LO3_E, A + LO3_O, 2051);             __syncthreads();
    sfb_p(A + LO3_E, A + LO3_O, B + LO2_E, B + LO2_O, 4099);             __syncthreads();
    sfb_p(B + LO2_E, B + LO2_O, A + LO1_E, A + LO1_O, 8194);             __syncthreads();

    // Final: 16384 pairs, natural-order GMEM output, season = x - trend
    float* tre = trend + off;
    float* sea = season + off;
    const float* Ei = A + LO1_E;
    const float* Oi = A + LO1_O;
    for (int c = threadIdx.x; c < 4096; c += THREADS) {
        const int m0 = c << 1;
        float4 te, to;
        SFB_CHUNK(Ei, Oi, m0, te, to);
        const int n0 = c << 3;
        const float4 t0 = make_float4(te.x, to.x, te.y, to.y);
        const float4 t1 = make_float4(te.z, to.z, te.w, to.w);
        *reinterpret_cast<float4*>(tre + n0)     = t0;
        *reinterpret_cast<float4*>(tre + n0 + 4) = t1;
        const float4 x0 = __ldg(reinterpret_cast<const float4*>(xr + n0));
        const float4 x1 = __ldg(reinterpret_cast<const float4*>(xr + n0 + 4));
        *reinterpret_cast<float4*>(sea + n0) =
            make_float4(x0.x - t0.x, x0.y - t0.y, x0.z - t0.z, x0.w - t0.w);
        *reinterpret_cast<float4*>(sea + n0 + 4) =
            make_float4(x1.x - t1.x, x1.y - t1.y, x1.z - t1.z, x1.w - t1.w);
    }
}

extern "C" void kernel_launch(void* const* d_in, const int* in_sizes, int n_in,
                              void* d_out, int out_size) {
    (void)n_in; (void)out_size;
    const float* x = (const float*)d_in[0];
    float* out = (float*)d_out;

    const int nsig = in_sizes[0] / 32768;
    const size_t total = (size_t)nsig * 32768;
    float* season = out;            // output tuple order: (season, trend)
    float* trend  = out + total;

    cudaFuncSetAttribute(wt_decomp_kernel,
                         cudaFuncAttributeMaxDynamicSharedMemorySize, SMEM_BYTES);
    wt_decomp_kernel<<<nsig, THREADS, SMEM_BYTES>>>(x, season, trend);
}